// round 9
// baseline (speedup 1.0000x reference)
#include <cuda_runtime.h>
#include <cstdint>
#include <climits>

// ---------------- problem constants (match reference exactly) ----------------
#define BB   4
#define NPTS 300000
#define NC   5
#define GXX  432
#define GYY  496
#define GZZ  1
#define NVOX (GXX * GYY * GZZ)          // 214272 (divisible by 4)
#define MAXV 40000
#define MAXP 30
#define CAP  48                          // per-voxel index bucket capacity
#define CHUNK 1024
#define NB   ((NVOX + CHUNK - 1) / CHUNK)   // 210

#define FEATS_ELEMS ((size_t)BB * MAXV * MAXP * NC)   // 24,000,000 floats
#define F4_FEATS (24000000 / 4)          // 6,000,000 float4
#define F4_COORD ((BB * MAXV * 4) / 4)   // 160,000 float4

#define I4_CELL  ((BB * NVOX) / 2)       // g_cell (int2) viewed as int4
#define I4_AGG   ((BB * NB + 3) / 4)
#define FILL_TOTAL (I4_CELL + I4_AGG + F4_COORD)

#define VALIDF (1 << 30)
#define ROWF   (MAXP * NC)               // 150 floats per feats row
#define PPT    4                          // points per scatter thread
#define NT     (NPTS / PPT)               // 75000

// ---------------- static device scratch ----------------------------------------
__device__ int2 g_cell  [BB * NVOX];     // .x = count, .y = rank
__device__ int4 g_agg4  [I4_AGG];
__device__ int  g_bucket[(size_t)BB * NVOX * CAP];

#define G_AGG ((int*)g_agg4)

// ---------------- init: cell {0,0}, agg 0, coords -1 ---------------------------
__global__ void k_fill(float4* __restrict__ out4) {
    int i = blockIdx.x * blockDim.x + threadIdx.x;
    if (i < I4_CELL) { ((int4*)g_cell)[i] = make_int4(0, 0, 0, 0); return; }
    i -= I4_CELL;
    if (i < I4_AGG) { g_agg4[i] = make_int4(0, 0, 0, 0); return; }
    i -= I4_AGG;
    if (i < F4_COORD) out4[F4_FEATS + i] = make_float4(-1.f, -1.f, -1.f, -1.f);
}

// ---------------- zero the 96MB feats region (pure streaming) -------------------
__global__ void k_zero(float4* __restrict__ feats4) {
    int tid = blockIdx.x * blockDim.x + threadIdx.x;
    int nthreads = gridDim.x * blockDim.x;
    const float4 z4 = make_float4(0.f, 0.f, 0.f, 0.f);
    for (int i = tid; i < F4_FEATS; i += nthreads) feats4[i] = z4;
}

// ---------------- pass 1: voxelize + bucket append ----------------------------
__global__ void k_points(const float* __restrict__ pts) {
    int tid = blockIdx.x * blockDim.x + threadIdx.x;
    if (tid >= BB * NPTS) return;
    int b = tid / NPTS;
    int n = tid - b * NPTS;
    const float* p = pts + (size_t)tid * NC;
    float x = __ldg(p + 0), y = __ldg(p + 1), z = __ldg(p + 2);
    // identical float32 ops as reference: floor((p - lo) / vs)
    int ix = (int)floorf((x - 0.0f)   / 0.16f);
    int iy = (int)floorf((y + 39.68f) / 0.16f);
    int iz = (int)floorf((z + 3.0f)   / 4.0f);
    if (ix < 0 || ix >= GXX || iy < 0 || iy >= GYY || iz < 0 || iz >= GZZ) return;
    int vid = (iz * GYY + iy) * GXX + ix;
    int cell = b * NVOX + vid;
    int pos = atomicAdd(&g_cell[cell].x, 1);
    if (pos < CAP) g_bucket[(size_t)cell * CAP + pos] = n;
}

// ---------------- single-pass scan with decoupled lookback --------------------
// 840 blocks (256 thr) all fit in one wave on 148 SMs -> spin-wait is safe.
// Writes per-cell rank (g_cell[].y) AND the coords rows (coords = f(vid, rank)).
__global__ void k_scan(float* __restrict__ out) {
    int blk = blockIdx.x;
    int b  = blk / NB;
    int cb = blk - b * NB;
    int t  = threadIdx.x;
    __shared__ int sh[256];

    int base = cb * CHUNK + t * 4;           // multiple of 4; NVOX % 4 == 0
    int f0 = 0, f1 = 0, f2 = 0, f3 = 0;
    if (base < NVOX) {
        const int4* p4 = (const int4*)g_cell + ((size_t)(b * NVOX + base) >> 1);
        int4 q0 = __ldg(p4 + 0);             // cells base, base+1
        int4 q1 = __ldg(p4 + 1);             // cells base+2, base+3
        f0 = (q0.x > 0); f1 = (q0.z > 0);
        f2 = (q1.x > 0); f3 = (q1.z > 0);
    }
    int s = f0 + f1 + f2 + f3;
    sh[t] = s;
    __syncthreads();
    #pragma unroll
    for (int off = 1; off < 256; off <<= 1) {   // Hillis–Steele inclusive
        int v = (t >= off) ? sh[t - off] : 0;
        __syncthreads();
        sh[t] += v;
        __syncthreads();
    }
    int excl  = sh[t] - s;
    int total = sh[255];

    // publish this chunk's aggregate ASAP
    if (t == 0) atomicExch(&G_AGG[blk], total | VALIDF);

    // lookback: sum all predecessor aggregates (within this batch)
    int partial = 0;
    for (int j = t; j < cb; j += 256) {
        int v;
        do { v = atomicAdd(&G_AGG[b * NB + j], 0); } while (!(v & VALIDF));
        partial += (v & (VALIDF - 1));
    }
    __syncthreads();
    sh[t] = partial;
    __syncthreads();
    #pragma unroll
    for (int off = 128; off > 0; off >>= 1) {
        if (t < off) sh[t] += sh[t + off];
        __syncthreads();
    }
    int r = sh[0] + excl;

    float4* coords = (float4*)(out + FEATS_ELEMS);
    #pragma unroll
    for (int q = 0; q < 4; q++) {
        int f = (q == 0) ? f0 : (q == 1) ? f1 : (q == 2) ? f2 : f3;
        if (f) {
            int vid = base + q;
            g_cell[b * NVOX + vid].y = r;
            if (r < MAXV) {
                int izc = vid / (GXX * GYY);
                int rem = vid - izc * (GXX * GYY);
                coords[b * MAXV + r] = make_float4((float)b, (float)izc,
                                                   (float)(rem / GXX),
                                                   (float)(rem % GXX));
            }
            r++;
        }
    }
}

// ---------------- scatter: 4 points per thread (4x MLP on the ci chain) --------
__global__ void k_scatter(const float* __restrict__ pts, float* __restrict__ out) {
    int tid = blockIdx.x * blockDim.x + threadIdx.x;
    if (tid >= BB * NT) return;
    int b  = tid / NT;
    int n0 = (tid - b * NT) * PPT;
    const float* pb = pts + ((size_t)b * NPTS + n0) * NC;

    float x[PPT], y[PPT], z[PPT];
    int   cell[PPT];
    bool  ok[PPT];
    #pragma unroll
    for (int k = 0; k < PPT; k++) {
        x[k] = __ldg(pb + k * NC + 0);
        y[k] = __ldg(pb + k * NC + 1);
        z[k] = __ldg(pb + k * NC + 2);
    }
    #pragma unroll
    for (int k = 0; k < PPT; k++) {
        int ix = (int)floorf((x[k] - 0.0f)   / 0.16f);
        int iy = (int)floorf((y[k] + 39.68f) / 0.16f);
        int iz = (int)floorf((z[k] + 3.0f)   / 4.0f);
        ok[k] = !(ix < 0 || ix >= GXX || iy < 0 || iy >= GYY || iz < 0 || iz >= GZZ);
        int vid = (iz * GYY + iy) * GXX + ix;
        cell[k] = ok[k] ? (b * NVOX + vid) : 0;   // safe dummy address
    }

    // 4 independent ci loads + 4 first-entry prefetches, all in flight at once
    int2 ci[PPT];
    int  e0[PPT];
    #pragma unroll
    for (int k = 0; k < PPT; k++) ci[k] = __ldg(&g_cell[cell[k]]);
    #pragma unroll
    for (int k = 0; k < PPT; k++) e0[k] = __ldg(g_bucket + (size_t)cell[k] * CAP);

    #pragma unroll
    for (int k = 0; k < PPT; k++) {
        if (!ok[k] || ci[k].y >= MAXV) continue;
        int n = n0 + k;
        int m = ci[k].x < CAP ? ci[k].x : CAP;
        const int* bk = g_bucket + (size_t)cell[k] * CAP;
        int r = (e0[k] < n);
        bool found = (e0[k] == n);
        for (int j = 1; j < m; j++) {
            int e = __ldg(bk + j);
            r += (e < n);
            found |= (e == n);
        }
        if (!found || r >= MAXP) continue;    // overflow-dropped or beyond 30

        float* fo = out + ((size_t)(b * MAXV + ci[k].y)) * ROWF + r * NC;
        fo[0] = (x[k] - 0.0f)   / 69.12f;
        fo[1] = (y[k] + 39.68f) / 79.36f;
        fo[2] = (z[k] + 3.0f)   / 4.0f;
        fo[3] = __ldg(pb + k * NC + 3);
        fo[4] = __ldg(pb + k * NC + 4);
    }
}

// ---------------- launch: strictly serial ----------------------------------------
extern "C" void kernel_launch(void* const* d_in, const int* in_sizes, int n_in,
                              void* d_out, int out_size) {
    const float* pts = (const float*)d_in[0];
    float* out = (float*)d_out;

    k_fill   <<<(FILL_TOTAL + 255) / 256, 256>>>((float4*)out);
    k_zero   <<<2048, 256>>>((float4*)out);
    k_points <<<(BB * NPTS + 255) / 256, 256>>>(pts);
    k_scan   <<<BB * NB, 256>>>(out);
    k_scatter<<<(BB * NT + 255) / 256, 256>>>(pts, out);
}

// round 10
// speedup vs baseline: 1.1722x; 1.1722x over previous
#include <cuda_runtime.h>
#include <cstdint>
#include <climits>

// ---------------- problem constants (match reference exactly) ----------------
#define BB   4
#define NPTS 300000
#define NC   5
#define GXX  432
#define GYY  496
#define GZZ  1
#define NVOX (GXX * GYY * GZZ)          // 214272 (divisible by 4)
#define MAXV 40000
#define MAXP 30
#define CAP  48                          // per-voxel index bucket capacity
#define CHUNK 4096
#define NB   ((NVOX + CHUNK - 1) / CHUNK)   // 53

#define FEATS_ELEMS ((size_t)BB * MAXV * MAXP * NC)   // 24,000,000 floats
#define F4_FEATS (24000000 / 4)          // 6,000,000 float4
#define F4_COORD ((BB * MAXV * 4) / 4)   // 160,000 float4

#define I4_CNT   ((BB * NVOX) / 4)       // 214,272 int4
#define I4_AGG   ((BB * NB + 3) / 4)
#define FILL_TOTAL (I4_CNT + I4_AGG + F4_COORD)

#define VALIDF (1 << 30)
#define ROWF   (MAXP * NC)               // 150 floats per feats row

// ---------------- static device scratch (16B-aligned for vector ops) ----------
__device__ int4 g_count4[(BB * NVOX) / 4];
__device__ int4 g_agg4  [I4_AGG];
__device__ int  g_rank  [BB * NVOX];     // cell -> absolute rank among occupied
__device__ int  g_bucket[(size_t)BB * NVOX * CAP];

#define G_COUNT ((int*)g_count4)
#define G_AGG   ((int*)g_agg4)

// ---------------- init: counts=0, agg=0, coords=-1 -----------------------------
__global__ void k_fill(float4* __restrict__ out4) {
    int i = blockIdx.x * blockDim.x + threadIdx.x;
    if (i < I4_CNT) { g_count4[i] = make_int4(0, 0, 0, 0); return; }
    i -= I4_CNT;
    if (i < I4_AGG) { g_agg4[i] = make_int4(0, 0, 0, 0); return; }
    i -= I4_AGG;
    if (i < F4_COORD) {
        out4[F4_FEATS + i] = make_float4(-1.f, -1.f, -1.f, -1.f);
    }
}

// ---------------- pass 1: voxelize + bucket append + feats zero ----------------
__global__ void k_points(const float* __restrict__ pts, float4* __restrict__ feats4) {
    int tid = blockIdx.x * blockDim.x + threadIdx.x;
    int nthreads = gridDim.x * blockDim.x;

    // issue the point loads first (long-latency, scoreboarded)
    float x = 0.f, y = 0.f, z = 0.f;
    bool havept = tid < BB * NPTS;
    if (havept) {
        const float* p = pts + (size_t)tid * NC;
        x = __ldg(p + 0); y = __ldg(p + 1); z = __ldg(p + 2);
    }

    // zero the feats region (unavoidable 96MB of streaming stores)
    const float4 z4 = make_float4(0.f, 0.f, 0.f, 0.f);
    for (int i = tid; i < F4_FEATS; i += nthreads) feats4[i] = z4;

    if (!havept) return;
    int b = tid / NPTS;
    int n = tid - b * NPTS;
    // identical float32 ops as reference: floor((p - lo) / vs)
    int ix = (int)floorf((x - 0.0f)   / 0.16f);
    int iy = (int)floorf((y + 39.68f) / 0.16f);
    int iz = (int)floorf((z + 3.0f)   / 4.0f);
    if (ix < 0 || ix >= GXX || iy < 0 || iy >= GYY || iz < 0 || iz >= GZZ) return;
    int vid = (iz * GYY + iy) * GXX + ix;
    int cell = b * NVOX + vid;
    int pos = atomicAdd(&G_COUNT[cell], 1);
    if (pos < CAP) g_bucket[(size_t)cell * CAP + pos] = n;
}

// ---------------- single-pass scan with decoupled lookback --------------------
// 212 blocks (256 thr, 16 cells/thread) fit in one wave -> spin-wait is safe.
// Writes per-cell rank AND the coords rows directly (coords = f(vid, rank)).
__global__ void k_scan(float* __restrict__ out) {
    int blk = blockIdx.x;
    int b  = blk / NB;
    int cb = blk - b * NB;
    int t  = threadIdx.x;
    __shared__ int sh[256];

    int base = cb * CHUNK + t * 16;          // multiple of 4; NVOX % 4 == 0
    int f[16];
    int s = 0;
    #pragma unroll
    for (int q = 0; q < 16; q += 4) {
        if (base + q < NVOX) {
            int4 c4 = __ldg((const int4*)(G_COUNT + b * NVOX + base + q));
            f[q + 0] = (c4.x > 0);
            f[q + 1] = (c4.y > 0);
            f[q + 2] = (c4.z > 0);
            f[q + 3] = (c4.w > 0);
        } else {
            f[q + 0] = f[q + 1] = f[q + 2] = f[q + 3] = 0;
        }
        s += f[q + 0] + f[q + 1] + f[q + 2] + f[q + 3];
    }
    sh[t] = s;
    __syncthreads();
    #pragma unroll
    for (int off = 1; off < 256; off <<= 1) {   // Hillis–Steele inclusive
        int v = (t >= off) ? sh[t - off] : 0;
        __syncthreads();
        sh[t] += v;
        __syncthreads();
    }
    int excl  = sh[t] - s;
    int total = sh[255];

    // publish this chunk's aggregate ASAP
    if (t == 0) atomicExch(&G_AGG[blk], total | VALIDF);

    // lookback: sum all predecessor aggregates (within this batch, <= 52)
    int partial = 0;
    for (int j = t; j < cb; j += 256) {
        int v;
        do { v = atomicAdd(&G_AGG[b * NB + j], 0); } while (!(v & VALIDF));
        partial += (v & (VALIDF - 1));
    }
    __syncthreads();
    sh[t] = partial;
    __syncthreads();
    #pragma unroll
    for (int off = 128; off > 0; off >>= 1) {
        if (t < off) sh[t] += sh[t + off];
        __syncthreads();
    }
    int r = sh[0] + excl;

    float4* coords = (float4*)(out + FEATS_ELEMS);
    #pragma unroll
    for (int q = 0; q < 16; q++) {
        if (f[q]) {
            int vid = base + q;
            g_rank[b * NVOX + vid] = r;
            if (r < MAXV) {
                int izc = vid / (GXX * GYY);
                int rem = vid - izc * (GXX * GYY);
                coords[b * MAXV + r] = make_float4((float)b, (float)izc,
                                                   (float)(rem / GXX),
                                                   (float)(rem % GXX));
            }
            r++;
        }
    }
}

// ---------------- scatter: one thread per point --------------------------------
// Recomputes vid, looks up rank, derives original-order within-voxel rank by
// scanning the (tiny, L2-resident) bucket, writes this point's 5 floats.
__global__ void k_scatter(const float* __restrict__ pts, float* __restrict__ out) {
    int tid = blockIdx.x * blockDim.x + threadIdx.x;
    if (tid >= BB * NPTS) return;
    int b = tid / NPTS;
    int n = tid - b * NPTS;
    const float* p = pts + (size_t)tid * NC;
    float x = __ldg(p + 0), y = __ldg(p + 1), z = __ldg(p + 2);
    int ix = (int)floorf((x - 0.0f)   / 0.16f);
    int iy = (int)floorf((y + 39.68f) / 0.16f);
    int iz = (int)floorf((z + 3.0f)   / 4.0f);
    if (ix < 0 || ix >= GXX || iy < 0 || iy >= GYY || iz < 0 || iz >= GZZ) return;
    int vid = (iz * GYY + iy) * GXX + ix;
    int cell = b * NVOX + vid;

    int rank = __ldg(&g_rank[cell]);          // valid: this voxel is occupied
    if (rank >= MAXV) return;
    int cnt = __ldg(&G_COUNT[cell]);
    int m = cnt < CAP ? cnt : CAP;
    const int* bk = g_bucket + (size_t)cell * CAP;

    int r = 0;
    bool found = false;
    for (int j = 0; j < m; j++) {
        int e = __ldg(bk + j);
        r += (e < n);
        found |= (e == n);
    }
    if (!found || r >= MAXP) return;          // overflow-dropped or beyond 30

    float* fo = out + ((size_t)(b * MAXV + rank)) * ROWF + r * NC;
    fo[0] = (x - 0.0f)   / 69.12f;
    fo[1] = (y + 39.68f) / 79.36f;
    fo[2] = (z + 3.0f)   / 4.0f;
    fo[3] = __ldg(p + 3);
    fo[4] = __ldg(p + 4);
}

// ---------------- launch ------------------------------------------------------
extern "C" void kernel_launch(void* const* d_in, const int* in_sizes, int n_in,
                              void* d_out, int out_size) {
    const float* pts = (const float*)d_in[0];
    float* out = (float*)d_out;

    k_fill   <<<(FILL_TOTAL + 255) / 256, 256>>>((float4*)out);
    k_points <<<(BB * NPTS + 255) / 256, 256>>>(pts, (float4*)out);
    k_scan   <<<BB * NB, 256>>>(out);
    k_scatter<<<(BB * NPTS + 255) / 256, 256>>>(pts, out);
}